// round 14
// baseline (speedup 1.0000x reference)
#include <cuda_runtime.h>
#include <math.h>

#define NPLANETS      10
#define NEDGES_LOC    45
#define NT_PER_BLOCK  49
#define NPASS         7
#define EPB_PASS      315                             // edges per pass (= 45*7)
#define EDGES_PB      2205                            // 45 * 49
#define THREADS       320
#define HID           32
#define BSTRIDE       34                              // even: 8B-aligned bias pairs

typedef unsigned long long ull;

// Constant-memory weights, packed for fma.rn.f32x2 with zero repack movs.
__constant__ ull        cW1p[3 * 16];          // rows r,theta,phi as (k,k+1) pairs
__constant__ ulonglong2 cW2p[HID * HID / 4];   // 256 x (4 floats)
__constant__ ulonglong2 cb2p[HID / 4];
__constant__ ull        cW3x[16];              // (W3[2q][0], W3[2q+1][0])
__constant__ ull        cW3y[16];
__constant__ ull        cW3z[16];
__constant__ float      cb3[3];

// One prep kernel stages packed weight layouts directly into the constant
// bank via symbol addresses (replaces 7 graph memcpy nodes).
__global__ void prep_consts(const float* __restrict__ W1,
                            const float* __restrict__ W2,
                            const float* __restrict__ b2,
                            const float* __restrict__ W3,
                            const float* __restrict__ b3,
                            float* __restrict__ dW1p,
                            float* __restrict__ dW2p,
                            float* __restrict__ db2p,
                            float* __restrict__ dW3x,
                            float* __restrict__ dW3y,
                            float* __restrict__ dW3z,
                            float* __restrict__ db3)
{
    int i = threadIdx.x;
    for (int k = i; k < 3 * HID; k += blockDim.x)   dW1p[k] = W1[k];
    for (int k = i; k < HID * HID; k += blockDim.x) dW2p[k] = W2[k];
    if (i < HID) {
        db2p[i] = b2[i];
        dW3x[i] = W3[i * 3 + 0];
        dW3y[i] = W3[i * 3 + 1];
        dW3z[i] = W3[i * 3 + 2];
    }
    if (i < 3) db3[i] = b3[i];
}

__device__ __forceinline__ float tanha(float x) {
    float y; asm("tanh.approx.f32 %0, %1;" : "=f"(y) : "f"(x));
    return y;
}
__device__ __forceinline__ ull pk2(float x) {
    ull d; unsigned u = __float_as_uint(x);
    asm("mov.b64 %0, {%1, %1};" : "=l"(d) : "r"(u));
    return d;
}
__device__ __forceinline__ ull pkab(float a, float b) {
    ull d;
    asm("mov.b64 %0, {%1, %2};" : "=l"(d) : "r"(__float_as_uint(a)), "r"(__float_as_uint(b)));
    return d;
}
__device__ __forceinline__ ull fma2(ull a, ull b, ull c) {
    ull d; asm("fma.rn.f32x2 %0, %1, %2, %3;" : "=l"(d) : "l"(a), "l"(b), "l"(c));
    return d;
}
__device__ __forceinline__ void upk(ull v, float& lo, float& hi) {
    unsigned a, b;
    asm("mov.b64 {%0, %1}, %2;" : "=r"(a), "=r"(b) : "l"(v));
    lo = __uint_as_float(a); hi = __uint_as_float(b);
}

// acos via A&S 4.4.45 (abs err <= 6.7e-5 rad)
__device__ __forceinline__ float acos_f(float x) {
    float ax = fabsf(x);
    float sq = sqrtf(1.0f - ax);
    float p  = fmaf(ax, fmaf(ax, fmaf(ax, -0.0187293f, 0.0742610f),
                             -0.2121144f), 1.5707288f);
    float th = sq * p;
    return (x < 0.0f) ? (3.14159274f - th) : th;
}
// atan2 via degree-11 minimax + quadrant fixup (err ~1e-5 rad)
__device__ __forceinline__ float atan2_f(float y, float x) {
    float ax = fabsf(x), ay = fabsf(y);
    float mn = fminf(ax, ay), mx = fmaxf(ax, ay);
    float a  = __fdividef(mn, mx);
    float s  = a * a;
    float t  = fmaf(s, fmaf(s, fmaf(s, fmaf(s, fmaf(s, -0.01172120f, 0.05265332f),
                    -0.11643287f), 0.19354346f), -0.33262347f), 0.99997726f) * a;
    if (ay > ax)   t = 1.57079637f - t;
    if (x < 0.0f)  t = 3.14159274f - t;
    return copysignf(t, y);
}

__global__ void __launch_bounds__(THREADS, 4)
learnforces_kernel(const float* __restrict__ D_V,
                   const float* __restrict__ logm,
                   const float* __restrict__ W1,
                   const float* __restrict__ b1,
                   const int*   __restrict__ senders,
                   const int*   __restrict__ receivers,
                   float*       __restrict__ out,
                   int ntime)
{
    __shared__ __align__(8) float sbias1[NEDGES_LOC * BSTRIDE];
    __shared__ float s_lm[NPLANETS];
    __shared__ float s_invm[NPLANETS];
    __shared__ int   s_snd[NEDGES_LOC];
    __shared__ int   s_rcv[NEDGES_LOC];
    __shared__ int   s_glist[NPLANETS][9];
    __shared__ __align__(16) float4 s_e[EDGES_PB];

    const int tid = threadIdx.x;

    // ---- cooperative setup (amortized over 49 timesteps) ----
    if (tid < NEDGES_LOC) { s_snd[tid] = senders[tid]; s_rcv[tid] = receivers[tid]; }
    if (tid < NPLANETS) {
        float v = fminf(fmaxf(logm[tid], -12.0f), 12.0f);
        s_lm[tid]   = v;
        s_invm[tid] = expf(-v);
    }
    __syncthreads();

    if (tid < NPLANETS) {
        int cnt = 0;
        for (int le = 0; le < NEDGES_LOC; le++) {
            if (s_rcv[le] == tid) s_glist[tid][cnt++] =  (le + 1);
            else if (s_snd[le] == tid) s_glist[tid][cnt++] = -(le + 1);
        }
    }
    // bias1 table: b1 + lm[r]*W1row3 + lm[s]*W1row4  (stride 34)
    for (int i = tid; i < NEDGES_LOC * HID; i += THREADS) {
        int le = i >> 5;
        int j  = i & 31;
        sbias1[le * BSTRIDE + j] = b1[j] + s_lm[s_rcv[le]] * W1[3 * HID + j]
                                         + s_lm[s_snd[le]] * W1[4 * HID + j];
    }
    __syncthreads();

    // ---- pass-invariant decomposition: eidx = pass*315 + tid, 315 = 7*45
    //      -> le = tid % 45 (invariant), t_local = pass*7 + tid/45
    const bool edge_thread = (tid < EPB_PASS);
    const unsigned tq  = (unsigned)tid / NEDGES_LOC;        // 0..6
    const unsigned le  = (unsigned)tid - tq * NEDGES_LOC;   // 0..44
    const ull* bias2   = (const ull*)(sbias1 + le * BSTRIDE);
    const unsigned blk_t0 = (unsigned)blockIdx.x * NT_PER_BLOCK;
    const unsigned t_base = blk_t0 + tq;
    const float* dv = D_V + ((size_t)blockIdx.x * EDGES_PB + tid) * 3u;

    // prefetch pass 0 inputs
    float x = 0.f, y = 0.f, z = 0.f;
    if (edge_thread && t_base < (unsigned)ntime) {
        x = dv[0]; y = dv[1]; z = dv[2];
    }

#pragma unroll 1
    for (int pass = 0; pass < NPASS; pass++) {
        const unsigned t_glob = t_base + (unsigned)pass * (NPASS);   // pass*7
        const bool valid = edge_thread && (t_glob < (unsigned)ntime);

        // prefetch next pass's coordinates (overlaps with compute below)
        float nx = 0.f, ny = 0.f, nz = 0.f;
        if (pass + 1 < NPASS) {
            const float* dvn = dv + (size_t)(pass + 1) * EPB_PASS * 3u;
            if (edge_thread && (t_glob + NPASS) < (unsigned)ntime) {
                nx = dvn[0]; ny = dvn[1]; nz = dvn[2];
            }
        }

        if (valid) {
            float r2 = fmaf(x, x, fmaf(y, y, z * z));
            float r  = sqrtf(r2);
            float ct = fminf(fmaxf(__fdividef(z, r), -1.0f), 1.0f);
            float th = acos_f(ct);
            float ph = atan2_f(y, x);

            ull rp = pk2(r), tp = pk2(th), pp = pk2(ph);

            // fused layer1+layer2, packed f32x2 (k-pairs)
            ull acc[16];
#pragma unroll
            for (int q = 0; q < 8; q++) {
                ulonglong2 v = cb2p[q];
                acc[2*q] = v.x; acc[2*q+1] = v.y;
            }

#pragma unroll
            for (int q = 0; q < 16; q++) {
                ull pre2 = fma2(rp, cW1p[q],
                           fma2(tp, cW1p[16 + q],
                           fma2(pp, cW1p[32 + q], bias2[q])));
                float a, b;
                upk(pre2, a, b);
                ull h0 = pk2(tanha(a));
                ull h1 = pk2(tanha(b));
                int k0 = 2 * q, k1 = 2 * q + 1;
#pragma unroll
                for (int j = 0; j < 8; j++) {
                    ulonglong2 w = cW2p[k0 * 8 + j];
                    acc[2*j]   = fma2(h0, w.x, acc[2*j]);
                    acc[2*j+1] = fma2(h0, w.y, acc[2*j+1]);
                }
#pragma unroll
                for (int j = 0; j < 8; j++) {
                    ulonglong2 w = cW2p[k1 * 8 + j];
                    acc[2*j]   = fma2(h1, w.x, acc[2*j]);
                    acc[2*j+1] = fma2(h1, w.y, acc[2*j+1]);
                }
            }

            // layer 3 packed: pair (tanh(lo),tanh(hi)) x column-pair tables
            ull ex2 = 0, ey2 = 0, ez2 = 0;
#pragma unroll
            for (int q = 0; q < 16; q++) {
                float lo, hi;
                upk(acc[q], lo, hi);
                ull hp = pkab(tanha(lo), tanha(hi));
                ex2 = fma2(hp, cW3x[q], ex2);
                ey2 = fma2(hp, cW3y[q], ey2);
                ez2 = fma2(hp, cW3z[q], ez2);
            }
            float e0, e1, e2, t0, t1;
            upk(ex2, t0, t1); e0 = t0 + t1 + cb3[0];
            upk(ey2, t0, t1); e1 = t0 + t1 + cb3[1];
            upk(ez2, t0, t1); e2 = t0 + t1 + cb3[2];

            // sph -> cart
            float st, ctq, sp, cp;
            __sincosf(e1, &st, &ctq);
            __sincosf(e2, &sp, &cp);
            float rs = e0 * st;
            s_e[pass * EPB_PASS + tid] = make_float4(rs * cp, rs * sp, e0 * ctq, 0.0f);
        }

        x = nx; y = ny; z = nz;
    }
    __syncthreads();

    // ---- gather-based scatter: 1470 items = 49 t * 10 planets * 3 comps ----
    for (int i = tid; i < NT_PER_BLOCK * NPLANETS * 3; i += THREADS) {
        int tl  = i / (NPLANETS * 3);
        int rem = i - tl * (NPLANETS * 3);
        int p   = rem / 3;
        int c   = rem - p * 3;
        unsigned t = blk_t0 + (unsigned)tl;
        if (t < (unsigned)ntime) {
            const float* eb = (const float*)(s_e + tl * NEDGES_LOC);
            float sum = 0.0f;
#pragma unroll
            for (int k = 0; k < 9; k++) {
                int gidx = s_glist[p][k];
                int lle  = (gidx > 0 ? gidx : -gidx) - 1;
                float v  = eb[lle * 4 + c];
                sum += (gidx > 0) ? v : -v;
            }
            out[t * (NPLANETS * 3) + rem] = sum * s_invm[p];
        }
    }
}

extern "C" void kernel_launch(void* const* d_in, const int* in_sizes, int n_in,
                              void* d_out, int out_size)
{
    const float* D_V       = (const float*)d_in[0];
    const float* logm      = (const float*)d_in[1];
    const float* W1        = (const float*)d_in[2];
    const float* b1        = (const float*)d_in[3];
    const float* W2        = (const float*)d_in[4];
    const float* b2        = (const float*)d_in[5];
    const float* W3        = (const float*)d_in[6];
    const float* b3        = (const float*)d_in[7];
    const int*   senders   = (const int*)d_in[8];
    const int*   receivers = (const int*)d_in[9];
    float*       out       = (float*)d_out;

    // Resolve constant-bank addresses (pure address queries; no allocation).
    void *pW1, *pW2, *pb2, *px, *py, *pz, *pb3;
    cudaGetSymbolAddress(&pW1, cW1p);
    cudaGetSymbolAddress(&pW2, cW2p);
    cudaGetSymbolAddress(&pb2, cb2p);
    cudaGetSymbolAddress(&px,  cW3x);
    cudaGetSymbolAddress(&py,  cW3y);
    cudaGetSymbolAddress(&pz,  cW3z);
    cudaGetSymbolAddress(&pb3, cb3);

    // One staging kernel instead of 7 memcpy graph nodes.
    prep_consts<<<1, 256>>>(W1, W2, b2, W3, b3,
                            (float*)pW1, (float*)pW2, (float*)pb2,
                            (float*)px, (float*)py, (float*)pz, (float*)pb3);

    int nedges = in_sizes[8];                  // 45
    int ntime  = in_sizes[0] / (3 * nedges);   // 100000

    int grid = (ntime + NT_PER_BLOCK - 1) / NT_PER_BLOCK;
    learnforces_kernel<<<grid, THREADS>>>(D_V, logm, W1, b1,
                                          senders, receivers, out, ntime);
}

// round 15
// speedup vs baseline: 1.0176x; 1.0176x over previous
#include <cuda_runtime.h>
#include <math.h>

#define NPLANETS      10
#define NEDGES_LOC    45
#define NT_PER_BLOCK  49
#define NPASS         7
#define EPB_PASS      315                             // edges per pass (= 45*7)
#define EDGES_PB      2205                            // 45 * 49
#define THREADS       320
#define HID           32
#define BSTRIDE       34                              // even: 8B-aligned bias pairs

typedef unsigned long long ull;

// Constant-memory weights, packed for fma.rn.f32x2 with zero repack movs.
__constant__ ull        cW1p[3 * 16];          // rows r,theta,phi as (k,k+1) pairs
__constant__ ulonglong2 cW2p[HID * HID / 4];   // 256 x (4 floats)
__constant__ ulonglong2 cb2p[HID / 4];
__constant__ ull        cW3x[16];              // (W3[2q][0], W3[2q+1][0])
__constant__ ull        cW3y[16];
__constant__ ull        cW3z[16];
__constant__ float      cb3[3];

// One prep kernel stages packed weight layouts directly into the constant
// bank via symbol addresses (replaces 7 graph memcpy nodes).
__global__ void prep_consts(const float* __restrict__ W1,
                            const float* __restrict__ W2,
                            const float* __restrict__ b2,
                            const float* __restrict__ W3,
                            const float* __restrict__ b3,
                            float* __restrict__ dW1p,
                            float* __restrict__ dW2p,
                            float* __restrict__ db2p,
                            float* __restrict__ dW3x,
                            float* __restrict__ dW3y,
                            float* __restrict__ dW3z,
                            float* __restrict__ db3)
{
    int i = threadIdx.x;
    for (int k = i; k < 3 * HID; k += blockDim.x)   dW1p[k] = W1[k];
    for (int k = i; k < HID * HID; k += blockDim.x) dW2p[k] = W2[k];
    if (i < HID) {
        db2p[i] = b2[i];
        dW3x[i] = W3[i * 3 + 0];
        dW3y[i] = W3[i * 3 + 1];
        dW3z[i] = W3[i * 3 + 2];
    }
    if (i < 3) db3[i] = b3[i];
}

__device__ __forceinline__ float tanha(float x) {
    float y; asm("tanh.approx.f32 %0, %1;" : "=f"(y) : "f"(x));
    return y;
}
__device__ __forceinline__ ull pk2(float x) {
    ull d; unsigned u = __float_as_uint(x);
    asm("mov.b64 %0, {%1, %1};" : "=l"(d) : "r"(u));
    return d;
}
__device__ __forceinline__ ull pkab(float a, float b) {
    ull d;
    asm("mov.b64 %0, {%1, %2};" : "=l"(d) : "r"(__float_as_uint(a)), "r"(__float_as_uint(b)));
    return d;
}
__device__ __forceinline__ ull fma2(ull a, ull b, ull c) {
    ull d; asm("fma.rn.f32x2 %0, %1, %2, %3;" : "=l"(d) : "l"(a), "l"(b), "l"(c));
    return d;
}
__device__ __forceinline__ void upk(ull v, float& lo, float& hi) {
    unsigned a, b;
    asm("mov.b64 {%0, %1}, %2;" : "=r"(a), "=r"(b) : "l"(v));
    lo = __uint_as_float(a); hi = __uint_as_float(b);
}

// acos via A&S 4.4.45 (abs err <= 6.7e-5 rad)
__device__ __forceinline__ float acos_f(float x) {
    float ax = fabsf(x);
    float sq = sqrtf(1.0f - ax);
    float p  = fmaf(ax, fmaf(ax, fmaf(ax, -0.0187293f, 0.0742610f),
                             -0.2121144f), 1.5707288f);
    float th = sq * p;
    return (x < 0.0f) ? (3.14159274f - th) : th;
}
// atan2 via degree-11 minimax + quadrant fixup (err ~1e-5 rad)
__device__ __forceinline__ float atan2_f(float y, float x) {
    float ax = fabsf(x), ay = fabsf(y);
    float mn = fminf(ax, ay), mx = fmaxf(ax, ay);
    float a  = __fdividef(mn, mx);
    float s  = a * a;
    float t  = fmaf(s, fmaf(s, fmaf(s, fmaf(s, fmaf(s, -0.01172120f, 0.05265332f),
                    -0.11643287f), 0.19354346f), -0.33262347f), 0.99997726f) * a;
    if (ay > ax)   t = 1.57079637f - t;
    if (x < 0.0f)  t = 3.14159274f - t;
    return copysignf(t, y);
}

__global__ void __launch_bounds__(THREADS, 4)
learnforces_kernel(const float* __restrict__ D_V,
                   const float* __restrict__ logm,
                   const float* __restrict__ W1,
                   const float* __restrict__ b1,
                   const int*   __restrict__ senders,
                   const int*   __restrict__ receivers,
                   float*       __restrict__ out,
                   int ntime)
{
    __shared__ __align__(8) float sbias1[NEDGES_LOC * BSTRIDE];
    __shared__ float s_lm[NPLANETS];
    __shared__ float s_invm[NPLANETS];
    __shared__ int   s_snd[NEDGES_LOC];
    __shared__ int   s_rcv[NEDGES_LOC];
    __shared__ int   s_glist[NPLANETS][9];
    __shared__ __align__(16) float4 s_e[EDGES_PB];

    const int tid = threadIdx.x;

    // ---- cooperative setup (amortized over 49 timesteps) ----
    if (tid < NEDGES_LOC) { s_snd[tid] = senders[tid]; s_rcv[tid] = receivers[tid]; }
    if (tid < NPLANETS) {
        float v = fminf(fmaxf(logm[tid], -12.0f), 12.0f);
        s_lm[tid]   = v;
        s_invm[tid] = expf(-v);
    }
    __syncthreads();

    if (tid < NPLANETS) {
        int cnt = 0;
        for (int le = 0; le < NEDGES_LOC; le++) {
            if (s_rcv[le] == tid) s_glist[tid][cnt++] =  (le + 1);
            else if (s_snd[le] == tid) s_glist[tid][cnt++] = -(le + 1);
        }
    }
    // bias1 table: b1 + lm[r]*W1row3 + lm[s]*W1row4  (stride 34)
    for (int i = tid; i < NEDGES_LOC * HID; i += THREADS) {
        int le = i >> 5;
        int j  = i & 31;
        sbias1[le * BSTRIDE + j] = b1[j] + s_lm[s_rcv[le]] * W1[3 * HID + j]
                                         + s_lm[s_snd[le]] * W1[4 * HID + j];
    }
    __syncthreads();

    // ---- pass-invariant decomposition: eidx = pass*315 + tid, 315 = 7*45
    //      -> le = tid % 45 (invariant), t_local = pass*7 + tid/45
    const bool edge_thread = (tid < EPB_PASS);
    const unsigned tq  = (unsigned)tid / NEDGES_LOC;        // 0..6
    const unsigned le  = (unsigned)tid - tq * NEDGES_LOC;   // 0..44
    const ull* bias2   = (const ull*)(sbias1 + le * BSTRIDE);
    const unsigned blk_t0 = (unsigned)blockIdx.x * NT_PER_BLOCK;
    const unsigned t_base = blk_t0 + tq;
    const float* dv = D_V + ((size_t)blockIdx.x * EDGES_PB + tid) * 3u;

#pragma unroll 1
    for (int pass = 0; pass < NPASS; pass++) {
        const unsigned t_glob = t_base + (unsigned)pass * NPASS;   // + pass*7

        if (edge_thread && t_glob < (unsigned)ntime) {
            const float* dvp = dv + (size_t)pass * EPB_PASS * 3u;
            float x = dvp[0];
            float y = dvp[1];
            float z = dvp[2];

            float r2 = fmaf(x, x, fmaf(y, y, z * z));
            float r  = sqrtf(r2);
            float ct = fminf(fmaxf(__fdividef(z, r), -1.0f), 1.0f);
            float th = acos_f(ct);
            float ph = atan2_f(y, x);

            ull rp = pk2(r), tp = pk2(th), pp = pk2(ph);

            // fused layer1+layer2, packed f32x2 (k-pairs)
            ull acc[16];
#pragma unroll
            for (int q = 0; q < 8; q++) {
                ulonglong2 v = cb2p[q];
                acc[2*q] = v.x; acc[2*q+1] = v.y;
            }

#pragma unroll
            for (int q = 0; q < 16; q++) {
                ull pre2 = fma2(rp, cW1p[q],
                           fma2(tp, cW1p[16 + q],
                           fma2(pp, cW1p[32 + q], bias2[q])));
                float a, b;
                upk(pre2, a, b);
                ull h0 = pk2(tanha(a));
                ull h1 = pk2(tanha(b));
                int k0 = 2 * q, k1 = 2 * q + 1;
#pragma unroll
                for (int j = 0; j < 8; j++) {
                    ulonglong2 w = cW2p[k0 * 8 + j];
                    acc[2*j]   = fma2(h0, w.x, acc[2*j]);
                    acc[2*j+1] = fma2(h0, w.y, acc[2*j+1]);
                }
#pragma unroll
                for (int j = 0; j < 8; j++) {
                    ulonglong2 w = cW2p[k1 * 8 + j];
                    acc[2*j]   = fma2(h1, w.x, acc[2*j]);
                    acc[2*j+1] = fma2(h1, w.y, acc[2*j+1]);
                }
            }

            // layer 3 packed: pair (tanh(lo),tanh(hi)) x column-pair tables
            ull ex2 = 0, ey2 = 0, ez2 = 0;
#pragma unroll
            for (int q = 0; q < 16; q++) {
                float lo, hi;
                upk(acc[q], lo, hi);
                ull hp = pkab(tanha(lo), tanha(hi));
                ex2 = fma2(hp, cW3x[q], ex2);
                ey2 = fma2(hp, cW3y[q], ey2);
                ez2 = fma2(hp, cW3z[q], ez2);
            }
            float e0, e1, e2, t0, t1;
            upk(ex2, t0, t1); e0 = t0 + t1 + cb3[0];
            upk(ey2, t0, t1); e1 = t0 + t1 + cb3[1];
            upk(ez2, t0, t1); e2 = t0 + t1 + cb3[2];

            // sph -> cart
            float st, ctq, sp, cp;
            __sincosf(e1, &st, &ctq);
            __sincosf(e2, &sp, &cp);
            float rs = e0 * st;
            s_e[pass * EPB_PASS + tid] = make_float4(rs * cp, rs * sp, e0 * ctq, 0.0f);
        }
    }
    __syncthreads();

    // ---- gather-based scatter: 1470 items = 49 t * 10 planets * 3 comps ----
    for (int i = tid; i < NT_PER_BLOCK * NPLANETS * 3; i += THREADS) {
        int tl  = i / (NPLANETS * 3);
        int rem = i - tl * (NPLANETS * 3);
        int p   = rem / 3;
        int c   = rem - p * 3;
        unsigned t = blk_t0 + (unsigned)tl;
        if (t < (unsigned)ntime) {
            const float* eb = (const float*)(s_e + tl * NEDGES_LOC);
            float sum = 0.0f;
#pragma unroll
            for (int k = 0; k < 9; k++) {
                int gidx = s_glist[p][k];
                int lle  = (gidx > 0 ? gidx : -gidx) - 1;
                float v  = eb[lle * 4 + c];
                sum += (gidx > 0) ? v : -v;
            }
            out[t * (NPLANETS * 3) + rem] = sum * s_invm[p];
        }
    }
}

extern "C" void kernel_launch(void* const* d_in, const int* in_sizes, int n_in,
                              void* d_out, int out_size)
{
    const float* D_V       = (const float*)d_in[0];
    const float* logm      = (const float*)d_in[1];
    const float* W1        = (const float*)d_in[2];
    const float* b1        = (const float*)d_in[3];
    const float* W2        = (const float*)d_in[4];
    const float* b2        = (const float*)d_in[5];
    const float* W3        = (const float*)d_in[6];
    const float* b3        = (const float*)d_in[7];
    const int*   senders   = (const int*)d_in[8];
    const int*   receivers = (const int*)d_in[9];
    float*       out       = (float*)d_out;

    // Resolve constant-bank addresses (pure address queries; no allocation).
    void *pW1, *pW2, *pb2, *px, *py, *pz, *pb3;
    cudaGetSymbolAddress(&pW1, cW1p);
    cudaGetSymbolAddress(&pW2, cW2p);
    cudaGetSymbolAddress(&pb2, cb2p);
    cudaGetSymbolAddress(&px,  cW3x);
    cudaGetSymbolAddress(&py,  cW3y);
    cudaGetSymbolAddress(&pz,  cW3z);
    cudaGetSymbolAddress(&pb3, cb3);

    // One staging kernel instead of 7 memcpy graph nodes.
    prep_consts<<<1, 256>>>(W1, W2, b2, W3, b3,
                            (float*)pW1, (float*)pW2, (float*)pb2,
                            (float*)px, (float*)py, (float*)pz, (float*)pb3);

    int nedges = in_sizes[8];                  // 45
    int ntime  = in_sizes[0] / (3 * nedges);   // 100000

    int grid = (ntime + NT_PER_BLOCK - 1) / NT_PER_BLOCK;
    learnforces_kernel<<<grid, THREADS>>>(D_V, logm, W1, b1,
                                          senders, receivers, out, ntime);
}

// round 16
// speedup vs baseline: 1.0312x; 1.0134x over previous
#include <cuda_runtime.h>
#include <math.h>

#define NPLANETS      10
#define NEDGES_LOC    45
#define NT_PER_BLOCK  56
#define NPASS         8
#define EPB_PASS      315                             // edges per pass (= 45*7)
#define TSTRIDE       7                               // timesteps per pass (= EPB_PASS/45)
#define EDGES_PB      2520                            // 45 * 56
#define THREADS       320
#define HID           32
#define BSTRIDE       34                              // even: 8B-aligned bias pairs

typedef unsigned long long ull;

// Constant-memory weights, packed for fma.rn.f32x2 with zero repack movs.
__constant__ ull        cW1p[3 * 16];          // rows r,theta,phi as (k,k+1) pairs
__constant__ ulonglong2 cW2p[HID * HID / 4];   // 256 x (4 floats)
__constant__ ulonglong2 cb2p[HID / 4];
__constant__ ull        cW3x[16];              // (W3[2q][0], W3[2q+1][0])
__constant__ ull        cW3y[16];
__constant__ ull        cW3z[16];
__constant__ float      cb3[3];

// One prep kernel stages packed weight layouts directly into the constant
// bank via symbol addresses (replaces 7 graph memcpy nodes).
__global__ void prep_consts(const float* __restrict__ W1,
                            const float* __restrict__ W2,
                            const float* __restrict__ b2,
                            const float* __restrict__ W3,
                            const float* __restrict__ b3,
                            float* __restrict__ dW1p,
                            float* __restrict__ dW2p,
                            float* __restrict__ db2p,
                            float* __restrict__ dW3x,
                            float* __restrict__ dW3y,
                            float* __restrict__ dW3z,
                            float* __restrict__ db3)
{
    int i = threadIdx.x;
    for (int k = i; k < 3 * HID; k += blockDim.x)   dW1p[k] = W1[k];
    for (int k = i; k < HID * HID; k += blockDim.x) dW2p[k] = W2[k];
    if (i < HID) {
        db2p[i] = b2[i];
        dW3x[i] = W3[i * 3 + 0];
        dW3y[i] = W3[i * 3 + 1];
        dW3z[i] = W3[i * 3 + 2];
    }
    if (i < 3) db3[i] = b3[i];
}

__device__ __forceinline__ float tanha(float x) {
    float y; asm("tanh.approx.f32 %0, %1;" : "=f"(y) : "f"(x));
    return y;
}
__device__ __forceinline__ ull pk2(float x) {
    ull d; unsigned u = __float_as_uint(x);
    asm("mov.b64 %0, {%1, %1};" : "=l"(d) : "r"(u));
    return d;
}
__device__ __forceinline__ ull pkab(float a, float b) {
    ull d;
    asm("mov.b64 %0, {%1, %2};" : "=l"(d) : "r"(__float_as_uint(a)), "r"(__float_as_uint(b)));
    return d;
}
__device__ __forceinline__ ull fma2(ull a, ull b, ull c) {
    ull d; asm("fma.rn.f32x2 %0, %1, %2, %3;" : "=l"(d) : "l"(a), "l"(b), "l"(c));
    return d;
}
__device__ __forceinline__ void upk(ull v, float& lo, float& hi) {
    unsigned a, b;
    asm("mov.b64 {%0, %1}, %2;" : "=r"(a), "=r"(b) : "l"(v));
    lo = __uint_as_float(a); hi = __uint_as_float(b);
}

// acos via A&S 4.4.45 (abs err <= 6.7e-5 rad)
__device__ __forceinline__ float acos_f(float x) {
    float ax = fabsf(x);
    float sq = sqrtf(1.0f - ax);
    float p  = fmaf(ax, fmaf(ax, fmaf(ax, -0.0187293f, 0.0742610f),
                             -0.2121144f), 1.5707288f);
    float th = sq * p;
    return (x < 0.0f) ? (3.14159274f - th) : th;
}
// atan2 via degree-11 minimax + quadrant fixup (err ~1e-5 rad)
__device__ __forceinline__ float atan2_f(float y, float x) {
    float ax = fabsf(x), ay = fabsf(y);
    float mn = fminf(ax, ay), mx = fmaxf(ax, ay);
    float a  = __fdividef(mn, mx);
    float s  = a * a;
    float t  = fmaf(s, fmaf(s, fmaf(s, fmaf(s, fmaf(s, -0.01172120f, 0.05265332f),
                    -0.11643287f), 0.19354346f), -0.33262347f), 0.99997726f) * a;
    if (ay > ax)   t = 1.57079637f - t;
    if (x < 0.0f)  t = 3.14159274f - t;
    return copysignf(t, y);
}

__global__ void __launch_bounds__(THREADS, 4)
learnforces_kernel(const float* __restrict__ D_V,
                   const float* __restrict__ logm,
                   const float* __restrict__ W1,
                   const float* __restrict__ b1,
                   const int*   __restrict__ senders,
                   const int*   __restrict__ receivers,
                   float*       __restrict__ out,
                   int ntime)
{
    __shared__ __align__(8) float sbias1[NEDGES_LOC * BSTRIDE];
    __shared__ float s_lm[NPLANETS];
    __shared__ float s_invm[NPLANETS];
    __shared__ int   s_snd[NEDGES_LOC];
    __shared__ int   s_rcv[NEDGES_LOC];
    __shared__ int   s_glist[NPLANETS][9];
    __shared__ __align__(16) float4 s_e[EDGES_PB];

    const int tid = threadIdx.x;

    // ---- cooperative setup (amortized over 56 timesteps) ----
    if (tid < NEDGES_LOC) { s_snd[tid] = senders[tid]; s_rcv[tid] = receivers[tid]; }
    if (tid < NPLANETS) {
        float v = fminf(fmaxf(logm[tid], -12.0f), 12.0f);
        s_lm[tid]   = v;
        s_invm[tid] = expf(-v);
    }
    __syncthreads();

    if (tid < NPLANETS) {
        int cnt = 0;
        for (int le = 0; le < NEDGES_LOC; le++) {
            if (s_rcv[le] == tid) s_glist[tid][cnt++] =  (le + 1);
            else if (s_snd[le] == tid) s_glist[tid][cnt++] = -(le + 1);
        }
    }
    // bias1 table: b1 + lm[r]*W1row3 + lm[s]*W1row4  (stride 34)
    for (int i = tid; i < NEDGES_LOC * HID; i += THREADS) {
        int le = i >> 5;
        int j  = i & 31;
        sbias1[le * BSTRIDE + j] = b1[j] + s_lm[s_rcv[le]] * W1[3 * HID + j]
                                         + s_lm[s_snd[le]] * W1[4 * HID + j];
    }
    __syncthreads();

    // ---- pass-invariant decomposition: eidx = pass*315 + tid, 315 = 7*45
    //      -> le = tid % 45 (invariant), t_local = pass*7 + tid/45
    const bool edge_thread = (tid < EPB_PASS);
    const unsigned tq  = (unsigned)tid / NEDGES_LOC;        // 0..6
    const unsigned le  = (unsigned)tid - tq * NEDGES_LOC;   // 0..44
    const ull* bias2   = (const ull*)(sbias1 + le * BSTRIDE);
    const unsigned blk_t0 = (unsigned)blockIdx.x * NT_PER_BLOCK;
    const unsigned t_base = blk_t0 + tq;
    const float* dv = D_V + ((size_t)blockIdx.x * EDGES_PB + tid) * 3u;

#pragma unroll 1
    for (int pass = 0; pass < NPASS; pass++) {
        const unsigned t_glob = t_base + (unsigned)pass * TSTRIDE;

        if (edge_thread && t_glob < (unsigned)ntime) {
            const float* dvp = dv + (size_t)pass * EPB_PASS * 3u;
            float x = dvp[0];
            float y = dvp[1];
            float z = dvp[2];

            float r2 = fmaf(x, x, fmaf(y, y, z * z));
            float r  = sqrtf(r2);
            float ct = fminf(fmaxf(__fdividef(z, r), -1.0f), 1.0f);
            float th = acos_f(ct);
            float ph = atan2_f(y, x);

            ull rp = pk2(r), tp = pk2(th), pp = pk2(ph);

            // fused layer1+layer2, packed f32x2 (k-pairs)
            ull acc[16];
#pragma unroll
            for (int q = 0; q < 8; q++) {
                ulonglong2 v = cb2p[q];
                acc[2*q] = v.x; acc[2*q+1] = v.y;
            }

#pragma unroll
            for (int q = 0; q < 16; q++) {
                ull pre2 = fma2(rp, cW1p[q],
                           fma2(tp, cW1p[16 + q],
                           fma2(pp, cW1p[32 + q], bias2[q])));
                float a, b;
                upk(pre2, a, b);
                ull h0 = pk2(tanha(a));
                ull h1 = pk2(tanha(b));
                int k0 = 2 * q, k1 = 2 * q + 1;
#pragma unroll
                for (int j = 0; j < 8; j++) {
                    ulonglong2 w = cW2p[k0 * 8 + j];
                    acc[2*j]   = fma2(h0, w.x, acc[2*j]);
                    acc[2*j+1] = fma2(h0, w.y, acc[2*j+1]);
                }
#pragma unroll
                for (int j = 0; j < 8; j++) {
                    ulonglong2 w = cW2p[k1 * 8 + j];
                    acc[2*j]   = fma2(h1, w.x, acc[2*j]);
                    acc[2*j+1] = fma2(h1, w.y, acc[2*j+1]);
                }
            }

            // layer 3 packed: pair (tanh(lo),tanh(hi)) x column-pair tables
            ull ex2 = 0, ey2 = 0, ez2 = 0;
#pragma unroll
            for (int q = 0; q < 16; q++) {
                float lo, hi;
                upk(acc[q], lo, hi);
                ull hp = pkab(tanha(lo), tanha(hi));
                ex2 = fma2(hp, cW3x[q], ex2);
                ey2 = fma2(hp, cW3y[q], ey2);
                ez2 = fma2(hp, cW3z[q], ez2);
            }
            float e0, e1, e2, t0, t1;
            upk(ex2, t0, t1); e0 = t0 + t1 + cb3[0];
            upk(ey2, t0, t1); e1 = t0 + t1 + cb3[1];
            upk(ez2, t0, t1); e2 = t0 + t1 + cb3[2];

            // sph -> cart
            float st, ctq, sp, cp;
            __sincosf(e1, &st, &ctq);
            __sincosf(e2, &sp, &cp);
            float rs = e0 * st;
            s_e[pass * EPB_PASS + tid] = make_float4(rs * cp, rs * sp, e0 * ctq, 0.0f);
        }
    }
    __syncthreads();

    // ---- gather-based scatter: 1680 items = 56 t * 10 planets * 3 comps ----
    for (int i = tid; i < NT_PER_BLOCK * NPLANETS * 3; i += THREADS) {
        int tl  = i / (NPLANETS * 3);
        int rem = i - tl * (NPLANETS * 3);
        int p   = rem / 3;
        int c   = rem - p * 3;
        unsigned t = blk_t0 + (unsigned)tl;
        if (t < (unsigned)ntime) {
            const float* eb = (const float*)(s_e + tl * NEDGES_LOC);
            float sum = 0.0f;
#pragma unroll
            for (int k = 0; k < 9; k++) {
                int gidx = s_glist[p][k];
                int lle  = (gidx > 0 ? gidx : -gidx) - 1;
                float v  = eb[lle * 4 + c];
                sum += (gidx > 0) ? v : -v;
            }
            out[t * (NPLANETS * 3) + rem] = sum * s_invm[p];
        }
    }
}

extern "C" void kernel_launch(void* const* d_in, const int* in_sizes, int n_in,
                              void* d_out, int out_size)
{
    const float* D_V       = (const float*)d_in[0];
    const float* logm      = (const float*)d_in[1];
    const float* W1        = (const float*)d_in[2];
    const float* b1        = (const float*)d_in[3];
    const float* W2        = (const float*)d_in[4];
    const float* b2        = (const float*)d_in[5];
    const float* W3        = (const float*)d_in[6];
    const float* b3        = (const float*)d_in[7];
    const int*   senders   = (const int*)d_in[8];
    const int*   receivers = (const int*)d_in[9];
    float*       out       = (float*)d_out;

    // Resolve constant-bank addresses (pure address queries; no allocation).
    void *pW1, *pW2, *pb2, *px, *py, *pz, *pb3;
    cudaGetSymbolAddress(&pW1, cW1p);
    cudaGetSymbolAddress(&pW2, cW2p);
    cudaGetSymbolAddress(&pb2, cb2p);
    cudaGetSymbolAddress(&px,  cW3x);
    cudaGetSymbolAddress(&py,  cW3y);
    cudaGetSymbolAddress(&pz,  cW3z);
    cudaGetSymbolAddress(&pb3, cb3);

    // One staging kernel instead of 7 memcpy graph nodes.
    prep_consts<<<1, 256>>>(W1, W2, b2, W3, b3,
                            (float*)pW1, (float*)pW2, (float*)pb2,
                            (float*)px, (float*)py, (float*)pz, (float*)pb3);

    int nedges = in_sizes[8];                  // 45
    int ntime  = in_sizes[0] / (3 * nedges);   // 100000

    int grid = (ntime + NT_PER_BLOCK - 1) / NT_PER_BLOCK;
    learnforces_kernel<<<grid, THREADS>>>(D_V, logm, W1, b1,
                                          senders, receivers, out, ntime);
}